// round 9
// baseline (speedup 1.0000x reference)
#include <cuda_runtime.h>

#define HH 56
#define WW 56
#define PP 3136   // HH*WW
#define BB 8
#define CC 64
#define KK 9      // 3x3

// Scratch (device globals: no allocation allowed in kernel_launch)
__device__ float g_xT[BB * PP * CC];    // x transposed: [b][p][c], c contiguous
__device__ float g_invn[BB * PP];       // 1/||x[b,:,p]||
__device__ int   g_sel[BB * PP * KK];   // sorted selected pixel indices
// W reordered: [k][m2][og][j], j 0..15: o = og*8 + (j>>1), c = 2*m2 + (j&1)
__device__ float g_wP[KK * 64 * 64];

// ---------------------------------------------------------------------------
// packed dual-FP32 FMA (Blackwell f32x2 path)
// ---------------------------------------------------------------------------
__device__ __forceinline__ float2 ffma2(float2 a, float2 b, float2 c) {
    unsigned long long A, Bv, Cv;
    A  = *reinterpret_cast<unsigned long long*>(&a);
    Bv = *reinterpret_cast<unsigned long long*>(&b);
    Cv = *reinterpret_cast<unsigned long long*>(&c);
    unsigned long long R;
    asm("fma.rn.f32x2 %0, %1, %2, %3;" : "=l"(R) : "l"(A), "l"(Bv), "l"(Cv));
    return *reinterpret_cast<float2*>(&R);
}

__device__ __forceinline__ void cp16(void* sdst, const void* gsrc) {
    unsigned sa = (unsigned)__cvta_generic_to_shared(sdst);
    asm volatile("cp.async.cg.shared.global [%0], [%1], 16;\n" :: "r"(sa), "l"(gsrc));
}

// ---------------------------------------------------------------------------
// 1) fused prep: blocks [0,784) transpose + invnorm; blocks [784,793) wprep
// ---------------------------------------------------------------------------
__global__ void __launch_bounds__(256)
prep_kernel(const float* __restrict__ x, const float* __restrict__ wgt) {
    const int id = blockIdx.x;
    const int t = threadIdx.x;

    if (id >= 784) {            // --- wprep: one block per k ---
        int k = id - 784;
#pragma unroll
        for (int s = 0; s < 16; s++) {
            int r = t * 16 + s;            // 0..4095
            int m2 = r >> 7, og = (r >> 4) & 7, j = r & 15;
            int o = og * 8 + (j >> 1);
            int c = 2 * m2 + (j & 1);
            g_wP[k * 4096 + r] = wgt[o * 576 + c * 9 + k];
        }
        return;
    }

    // --- transpose tile: 32 pixels x 64 channels ---
    __shared__ float s[64][37];
    int b = id / 98, pt = id - b * 98;
    int p0 = pt * 32;
    const float* xb = x + (size_t)b * CC * PP;
    float* xTb = g_xT + (size_t)b * PP * CC;

    int cl = t >> 3;        // 0..31
    int j4 = t & 7;         // float4 column within the 32 pixels
#pragma unroll
    for (int h = 0; h < 2; h++) {
        int c = cl + 32 * h;
        float4 v = *(const float4*)(xb + (size_t)c * PP + p0 + 4 * j4);
        s[c][4 * j4 + 0] = v.x; s[c][4 * j4 + 1] = v.y;
        s[c][4 * j4 + 2] = v.z; s[c][4 * j4 + 3] = v.w;
    }
    __syncthreads();

    int p = t >> 3, cq0 = t & 7;
#pragma unroll
    for (int h = 0; h < 2; h++) {
        int cq = cq0 + 8 * h;
        float4 v;
        v.x = s[4 * cq + 0][p]; v.y = s[4 * cq + 1][p];
        v.z = s[4 * cq + 2][p]; v.w = s[4 * cq + 3][p];
        *(float4*)(xTb + (size_t)(p0 + p) * CC + 4 * cq) = v;
    }

    // --- invnorm from the tile: 8 lanes per pixel ---
    float sum = 0.0f;
#pragma unroll
    for (int i = 0; i < 8; i++) {
        float v = s[cq0 * 8 + i][p];
        sum += v * v;
    }
    sum += __shfl_xor_sync(0xffffffffu, sum, 1);
    sum += __shfl_xor_sync(0xffffffffu, sum, 2);
    sum += __shfl_xor_sync(0xffffffffu, sum, 4);
    if (cq0 == 0) g_invn[b * PP + p0 + p] = 1.0f / sqrtf(sum);
}

// ---------------------------------------------------------------------------
// 3) simsel (unchanged from R7)
// ---------------------------------------------------------------------------
#define SROW 68   // smem row stride (floats)

__global__ void __launch_bounds__(256)
simsel2_kernel() {
    __shared__ __align__(16) float sn[60 * SROW];

    const int t = threadIdx.x;
    const int j0 = blockIdx.x * 8;      // 56/8 = 7 exact
    const int i  = blockIdx.y;
    const int b  = blockIdx.z;
    const float* xb   = g_xT + (size_t)b * PP * CC;
    const float* invb = g_invn + b * PP;

    {
        int slot = t >> 2, q = t & 3;
        if (slot < 60) {
            int ri = slot / 12, rj = slot - ri * 12;
            int gi = i - 2 + ri, gj = j0 - 2 + rj;
            if (gi >= 0 && gi < HH && gj >= 0 && gj < WW) {
                int gp = gi * WW + gj;
                const float* src = xb + (size_t)gp * CC;
                float iv = invb[gp];
                float* dst = sn + slot * SROW;
#pragma unroll
                for (int s = 0; s < 4; s++) {
                    int chunk = q + 4 * s;
                    float4 v = *(const float4*)(src + chunk * 4);
                    v.x *= iv; v.y *= iv; v.z *= iv; v.w *= iv;
                    *(float4*)(dst + 4 * ((chunk + ri) & 15)) = v;
                }
            }
        }
    }
    __syncthreads();

    const int lane = t & 31, w = t >> 5;
    const int j = j0 + w;

    int lo_i = (i - 2 < 0) ? 0 : i - 2;
    int hi_i = (i + 2 > HH - 1) ? HH - 1 : i + 2;
    int lo_j = (j - 2 < 0) ? 0 : j - 2;
    int hi_j = (j + 2 > WW - 1) ? WW - 1 : j + 2;
    int nrow = hi_i - lo_i + 1, ncol = hi_j - lo_j + 1;
    int ncand = nrow * ncol;

    unsigned mult = (65536u + (unsigned)ncol - 1) / (unsigned)ncol;
    int cr = (int)(((unsigned)lane * mult) >> 16);
    int cc = lane - cr * ncol;
    int ri = (lo_i - (i - 2)) + cr;
    int rj = (lo_j - (j0 - 2)) + cc;
    int slot = ri * 12 + rj;
    int rot_c = ri;
    if (lane >= ncand) { slot = 0; rot_c = 0; }
    int cpix = (lo_i + cr) * WW + (lo_j + cc);

    const float* crow = sn + slot * SROW;
    const float* prow = sn + (2 * 12 + (w + 2)) * SROW;   // rot_p = 2

    int idx_c = rot_c & 15;
    int idx_p = 2;

    float2 aA = make_float2(0.f, 0.f), aB = make_float2(0.f, 0.f);
#pragma unroll
    for (int s = 0; s < 16; s++) {
        float4 cv = *(const float4*)(crow + 4 * idx_c);
        float4 pv = *(const float4*)(prow + 4 * idx_p);
        aA = ffma2(make_float2(cv.x, cv.y), make_float2(pv.x, pv.y), aA);
        aB = ffma2(make_float2(cv.z, cv.w), make_float2(pv.z, pv.w), aB);
        idx_c = (idx_c + 1) & 15;
        idx_p = (idx_p + 1) & 15;
    }
    float sim = (aA.x + aB.x) + (aA.y + aB.y);

    unsigned ub = __float_as_uint(sim);
    unsigned key = (ub & 0x80000000u) ? ~ub : (ub | 0x80000000u);
    if (lane >= ncand) key = 0xFFFFFFFFu;

    int mypick = 0;
#pragma unroll
    for (int r = 0; r < KK; r++) {
        unsigned m = __reduce_min_sync(0xffffffffu, key);
        unsigned ball = __ballot_sync(0xffffffffu, key == m);
        int bl = __ffs(ball) - 1;
        int wc = __shfl_sync(0xffffffffu, cpix, bl);
        if (lane == bl) key = 0xFFFFFFFFu;
        if (lane == r) mypick = wc;
    }

    int rank = 0;
#pragma unroll
    for (int r = 0; r < KK; r++) {
        int other = __shfl_sync(0xffffffffu, mypick, r);
        if (lane < KK && r != lane && other < mypick) rank++;
    }
    if (lane < KK)
        g_sel[((size_t)(b * PP + i * WW + j)) * KK + rank] = mypick;
}

// ---------------------------------------------------------------------------
// 4) conv3: tile 64o x 64q, 64 threads, thread tile 8o x 8q, m-paired f32x2.
//    acc[o][q] is float2 over channel parity; G stored as {x[2m2],x[2m2+1]}
//    (no duplication); Ws og-groups padded to 20 floats -> conflict-free W
//    LDS.128 (banks {0,20,8,28,16,4,24,12}); G reads are per-phase broadcast.
//    Gd and Ws double-buffered; ONE barrier per k-chunk.
// ---------------------------------------------------------------------------
#define WS_CH 5120          // floats per Ws chunk buffer: 32 m2 x 8 og x 20
#define GR 130              // Gd floats per m2 row (65 float2: 64 q + pad)
#define GD_CH (32 * GR)     // 4160 floats
#define SEL3_B 2304
#define SMEM3 (SEL3_B + 2 * WS_CH * 4 + 2 * GD_CH * 4)   // 76544 B

__global__ void __launch_bounds__(64)
conv3_kernel(float* __restrict__ out) {
    extern __shared__ __align__(16) char smem_raw[];
    int*   selS = (int*)smem_raw;
    float* Ws   = (float*)(smem_raw + SEL3_B);
    float* Gd   = (float*)(smem_raw + SEL3_B + 2 * WS_CH * 4);

    const int tid  = threadIdx.x;
    const int tile = blockIdx.x;            // 392 tiles of 64 pixels
    const int b    = tile / 49;
    const int p0   = (tile % 49) * 64;
    const float* xb = g_xT + (size_t)b * PP * CC;

    // global pixel base = tile*64 (since 3136 = 49*64)
    for (int t = tid; t < 64 * KK; t += 64)
        selS[t] = g_sel[(size_t)tile * 64 * KK + t];

    const int u  = tid & 15, qr = tid >> 4;   // staging roles
    const int og = tid & 7,  qg = tid >> 3;   // compute roles
    const int o0 = og * 8,   q0 = qg * 8;

    float2 acc[8][8];
#pragma unroll
    for (int j = 0; j < 8; j++)
#pragma unroll
        for (int i = 0; i < 8; i++) acc[j][i] = make_float2(0.f, 0.f);

    float4 pg[8];

    auto cpW = [&](int kc, int bufi) {
        const float* src = g_wP + kc * 4096;
        float* dst = Ws + bufi * WS_CH;
#pragma unroll
        for (int i = 0; i < 16; i++) {
            int g = tid + i * 64;                  // float4 group 0..1023
            int m2 = g >> 5, r = g & 31;
            int og_ = r >> 2, c4 = r & 3;
            cp16(dst + m2 * 160 + og_ * 20 + c4 * 4, src + 4 * g);
        }
        asm volatile("cp.async.commit_group;\n");
    };

    auto stage_ld = [&](int kc, int t8) {
#pragma unroll
        for (int s = 0; s < 8; s++) {
            int q = qr * 16 + t8 * 8 + s;
            int row = selS[q * KK + kc];
            pg[s] = *(const float4*)(xb + (size_t)row * CC + u * 4);
        }
    };
    auto stage_st = [&](int bufi, int t8) {
        float* gd = Gd + bufi * GD_CH;
#pragma unroll
        for (int s = 0; s < 8; s++) {
            int q = qr * 16 + t8 * 8 + s;
            float4 v = pg[s];
            *(float2*)(gd + (2 * u    ) * GR + 2 * q) = make_float2(v.x, v.y);
            *(float2*)(gd + (2 * u + 1) * GR + 2 * q) = make_float2(v.z, v.w);
        }
    };

    auto compute_half = [&](const float* Wsb, const float* Gdb, int m2lo) {
#pragma unroll 4
        for (int mm = 0; mm < 16; mm++) {
            int m2 = m2lo + mm;
            const float* wrow = Wsb + m2 * 160 + og * 20;
            const float* grow = Gdb + m2 * GR + q0 * 2;
            float4 wq[4];
            float2 gq[8];
#pragma unroll
            for (int jj = 0; jj < 4; jj++)
                wq[jj] = *(const float4*)(wrow + 4 * jj);
#pragma unroll
            for (int ii = 0; ii < 8; ii++)
                gq[ii] = *(const float2*)(grow + 2 * ii);
#pragma unroll
            for (int jj = 0; jj < 4; jj++) {
                float2 wA = make_float2(wq[jj].x, wq[jj].y);
                float2 wB = make_float2(wq[jj].z, wq[jj].w);
#pragma unroll
                for (int ii = 0; ii < 8; ii++) {
                    acc[2 * jj][ii]     = ffma2(wA, gq[ii], acc[2 * jj][ii]);
                    acc[2 * jj + 1][ii] = ffma2(wB, gq[ii], acc[2 * jj + 1][ii]);
                }
            }
        }
    };

    // prologue: weights chunk 0 + gather chunk 0
    cpW(0, 0);
    __syncthreads();            // selS visible before stage_ld
    stage_ld(0, 0); stage_st(0, 0);
    stage_ld(0, 1); stage_st(0, 1);
    asm volatile("cp.async.wait_group 0;\n");
    __syncthreads();

    for (int kc = 0; kc < KK; kc++) {
        int buf = kc & 1;
        const float* Wsb = Ws + buf * WS_CH;
        const float* Gdb = Gd + buf * GD_CH;
        if (kc + 1 < KK) { cpW(kc + 1, buf ^ 1); stage_ld(kc + 1, 0); }
        compute_half(Wsb, Gdb, 0);
        if (kc + 1 < KK) { stage_st(buf ^ 1, 0); stage_ld(kc + 1, 1); }
        compute_half(Wsb, Gdb, 16);
        if (kc + 1 < KK) stage_st(buf ^ 1, 1);
        asm volatile("cp.async.wait_group 0;\n");
        __syncthreads();
    }

    // epilogue: out[b][o][p0+q], fold parity halves
    float* ob = out + (size_t)b * CC * PP + p0 + q0;
#pragma unroll
    for (int j = 0; j < 8; j++) {
        int o = o0 + j;
        float4 v0, v1;
        v0.x = acc[j][0].x + acc[j][0].y;
        v0.y = acc[j][1].x + acc[j][1].y;
        v0.z = acc[j][2].x + acc[j][2].y;
        v0.w = acc[j][3].x + acc[j][3].y;
        v1.x = acc[j][4].x + acc[j][4].y;
        v1.y = acc[j][5].x + acc[j][5].y;
        v1.z = acc[j][6].x + acc[j][6].y;
        v1.w = acc[j][7].x + acc[j][7].y;
        *(float4*)(ob + (size_t)o * PP)     = v0;
        *(float4*)(ob + (size_t)o * PP + 4) = v1;
    }
}

// ---------------------------------------------------------------------------
extern "C" void kernel_launch(void* const* d_in, const int* in_sizes, int n_in,
                              void* d_out, int out_size) {
    const float* x = (const float*)d_in[0];   // [8,64,56,56]
    const float* w = (const float*)d_in[1];   // [64,64,3,3]
    float* out = (float*)d_out;               // [8,64,56,56]

    cudaFuncSetAttribute(conv3_kernel,
                         cudaFuncAttributeMaxDynamicSharedMemorySize, SMEM3);

    prep_kernel<<<793, 256>>>(x, w);
    simsel2_kernel<<<dim3(7, 56, 8), 256>>>();
    conv3_kernel<<<392, 64, SMEM3>>>(out);
}

// round 10
// speedup vs baseline: 1.3311x; 1.3311x over previous
#include <cuda_runtime.h>

#define HH 56
#define WW 56
#define PP 3136   // HH*WW
#define BB 8
#define CC 64
#define KK 9      // 3x3

// Scratch (device globals: no allocation allowed in kernel_launch)
__device__ float g_xT[BB * PP * CC];    // x transposed: [b][p][c], c contiguous
__device__ float g_invn[BB * PP];       // 1/||x[b,:,p]||
__device__ int   g_sel[BB * PP * KK];   // sorted selected pixel indices
// W reordered: [k][m2][og][j], j 0..15: o = og*8 + (j>>1), c = 2*m2 + (j&1)
__device__ float g_wP[KK * 64 * 64];

// ---------------------------------------------------------------------------
// packed dual-FP32 FMA (Blackwell f32x2 path)
// ---------------------------------------------------------------------------
__device__ __forceinline__ float2 ffma2(float2 a, float2 b, float2 c) {
    unsigned long long A, Bv, Cv;
    A  = *reinterpret_cast<unsigned long long*>(&a);
    Bv = *reinterpret_cast<unsigned long long*>(&b);
    Cv = *reinterpret_cast<unsigned long long*>(&c);
    unsigned long long R;
    asm("fma.rn.f32x2 %0, %1, %2, %3;" : "=l"(R) : "l"(A), "l"(Bv), "l"(Cv));
    return *reinterpret_cast<float2*>(&R);
}

__device__ __forceinline__ void cp16(void* sdst, const void* gsrc) {
    unsigned sa = (unsigned)__cvta_generic_to_shared(sdst);
    asm volatile("cp.async.cg.shared.global [%0], [%1], 16;\n" :: "r"(sa), "l"(gsrc));
}

// ---------------------------------------------------------------------------
// 1) fused prep: blocks [0,784) transpose + invnorm; blocks [784,793) wprep
// ---------------------------------------------------------------------------
__global__ void __launch_bounds__(256)
prep_kernel(const float* __restrict__ x, const float* __restrict__ wgt) {
    const int id = blockIdx.x;
    const int t = threadIdx.x;

    if (id >= 784) {            // --- wprep: one block per k ---
        int k = id - 784;
#pragma unroll
        for (int s = 0; s < 16; s++) {
            int r = t * 16 + s;            // 0..4095
            int m2 = r >> 7, og = (r >> 4) & 7, j = r & 15;
            int o = og * 8 + (j >> 1);
            int c = 2 * m2 + (j & 1);
            g_wP[k * 4096 + r] = wgt[o * 576 + c * 9 + k];
        }
        return;
    }

    // --- transpose tile: 32 pixels x 64 channels ---
    __shared__ float s[64][37];
    int b = id / 98, pt = id - b * 98;
    int p0 = pt * 32;
    const float* xb = x + (size_t)b * CC * PP;
    float* xTb = g_xT + (size_t)b * PP * CC;

    int cl = t >> 3;        // 0..31
    int j4 = t & 7;         // float4 column within the 32 pixels
#pragma unroll
    for (int h = 0; h < 2; h++) {
        int c = cl + 32 * h;
        float4 v = *(const float4*)(xb + (size_t)c * PP + p0 + 4 * j4);
        s[c][4 * j4 + 0] = v.x; s[c][4 * j4 + 1] = v.y;
        s[c][4 * j4 + 2] = v.z; s[c][4 * j4 + 3] = v.w;
    }
    __syncthreads();

    int p = t >> 3, cq0 = t & 7;
#pragma unroll
    for (int h = 0; h < 2; h++) {
        int cq = cq0 + 8 * h;
        float4 v;
        v.x = s[4 * cq + 0][p]; v.y = s[4 * cq + 1][p];
        v.z = s[4 * cq + 2][p]; v.w = s[4 * cq + 3][p];
        *(float4*)(xTb + (size_t)(p0 + p) * CC + 4 * cq) = v;
    }

    // --- invnorm from the tile: 8 lanes per pixel ---
    float sum = 0.0f;
#pragma unroll
    for (int i = 0; i < 8; i++) {
        float v = s[cq0 * 8 + i][p];
        sum += v * v;
    }
    sum += __shfl_xor_sync(0xffffffffu, sum, 1);
    sum += __shfl_xor_sync(0xffffffffu, sum, 2);
    sum += __shfl_xor_sync(0xffffffffu, sum, 4);
    if (cq0 == 0) g_invn[b * PP + p0 + p] = 1.0f / sqrtf(sum);
}

// ---------------------------------------------------------------------------
// 3) simsel (unchanged from R7)
// ---------------------------------------------------------------------------
#define SROW 68   // smem row stride (floats)

__global__ void __launch_bounds__(256)
simsel2_kernel() {
    __shared__ __align__(16) float sn[60 * SROW];

    const int t = threadIdx.x;
    const int j0 = blockIdx.x * 8;      // 56/8 = 7 exact
    const int i  = blockIdx.y;
    const int b  = blockIdx.z;
    const float* xb   = g_xT + (size_t)b * PP * CC;
    const float* invb = g_invn + b * PP;

    {
        int slot = t >> 2, q = t & 3;
        if (slot < 60) {
            int ri = slot / 12, rj = slot - ri * 12;
            int gi = i - 2 + ri, gj = j0 - 2 + rj;
            if (gi >= 0 && gi < HH && gj >= 0 && gj < WW) {
                int gp = gi * WW + gj;
                const float* src = xb + (size_t)gp * CC;
                float iv = invb[gp];
                float* dst = sn + slot * SROW;
#pragma unroll
                for (int s = 0; s < 4; s++) {
                    int chunk = q + 4 * s;
                    float4 v = *(const float4*)(src + chunk * 4);
                    v.x *= iv; v.y *= iv; v.z *= iv; v.w *= iv;
                    *(float4*)(dst + 4 * ((chunk + ri) & 15)) = v;
                }
            }
        }
    }
    __syncthreads();

    const int lane = t & 31, w = t >> 5;
    const int j = j0 + w;

    int lo_i = (i - 2 < 0) ? 0 : i - 2;
    int hi_i = (i + 2 > HH - 1) ? HH - 1 : i + 2;
    int lo_j = (j - 2 < 0) ? 0 : j - 2;
    int hi_j = (j + 2 > WW - 1) ? WW - 1 : j + 2;
    int nrow = hi_i - lo_i + 1, ncol = hi_j - lo_j + 1;
    int ncand = nrow * ncol;

    unsigned mult = (65536u + (unsigned)ncol - 1) / (unsigned)ncol;
    int cr = (int)(((unsigned)lane * mult) >> 16);
    int cc = lane - cr * ncol;
    int ri = (lo_i - (i - 2)) + cr;
    int rj = (lo_j - (j0 - 2)) + cc;
    int slot = ri * 12 + rj;
    int rot_c = ri;
    if (lane >= ncand) { slot = 0; rot_c = 0; }
    int cpix = (lo_i + cr) * WW + (lo_j + cc);

    const float* crow = sn + slot * SROW;
    const float* prow = sn + (2 * 12 + (w + 2)) * SROW;   // rot_p = 2

    int idx_c = rot_c & 15;
    int idx_p = 2;

    float2 aA = make_float2(0.f, 0.f), aB = make_float2(0.f, 0.f);
#pragma unroll
    for (int s = 0; s < 16; s++) {
        float4 cv = *(const float4*)(crow + 4 * idx_c);
        float4 pv = *(const float4*)(prow + 4 * idx_p);
        aA = ffma2(make_float2(cv.x, cv.y), make_float2(pv.x, pv.y), aA);
        aB = ffma2(make_float2(cv.z, cv.w), make_float2(pv.z, pv.w), aB);
        idx_c = (idx_c + 1) & 15;
        idx_p = (idx_p + 1) & 15;
    }
    float sim = (aA.x + aB.x) + (aA.y + aB.y);

    unsigned ub = __float_as_uint(sim);
    unsigned key = (ub & 0x80000000u) ? ~ub : (ub | 0x80000000u);
    if (lane >= ncand) key = 0xFFFFFFFFu;

    int mypick = 0;
#pragma unroll
    for (int r = 0; r < KK; r++) {
        unsigned m = __reduce_min_sync(0xffffffffu, key);
        unsigned ball = __ballot_sync(0xffffffffu, key == m);
        int bl = __ffs(ball) - 1;
        int wc = __shfl_sync(0xffffffffu, cpix, bl);
        if (lane == bl) key = 0xFFFFFFFFu;
        if (lane == r) mypick = wc;
    }

    int rank = 0;
#pragma unroll
    for (int r = 0; r < KK; r++) {
        int other = __shfl_sync(0xffffffffu, mypick, r);
        if (lane < KK && r != lane && other < mypick) rank++;
    }
    if (lane < KK)
        g_sel[((size_t)(b * PP + i * WW + j)) * KK + rank] = mypick;
}

// ---------------------------------------------------------------------------
// 4) conv4: tile 64o x 64q, 128 threads (4 warps), thread tile 8o x 4q,
//    m-paired f32x2 (acc over channel parity, G stored as natural float2 of
//    adjacent channels -- no duplication). Ws og-groups padded to 20 floats
//    (banks {0,20,8,28,16,4,24,12} conflict-free); G reads: 16 consecutive
//    float2 per 16-lane phase = conflict-free. Ws double-buffered (cp.async),
//    Gd single-buffered; 2 barriers per k-chunk; 3 blocks/SM.
// ---------------------------------------------------------------------------
#define WS_CH 5120          // floats per Ws chunk buffer: 32 m2 x 8 og x 20
#define GR 130              // Gd floats per m2 row (65 float2: 64 q + pad)
#define SEL4_B 2304
#define SMEM4 (SEL4_B + 2 * WS_CH * 4 + 32 * GR * 4)   // 59904 B

__global__ void __launch_bounds__(128)
conv4_kernel(float* __restrict__ out) {
    extern __shared__ __align__(16) char smem_raw[];
    int*   selS = (int*)smem_raw;
    float* Ws   = (float*)(smem_raw + SEL4_B);
    float* Gd   = (float*)(smem_raw + SEL4_B + 2 * WS_CH * 4);

    const int tid  = threadIdx.x;
    const int tile = blockIdx.x;            // 392 tiles of 64 pixels
    const int b    = tile / 49;
    const int p0   = (tile % 49) * 64;
    const float* xb = g_xT + (size_t)b * PP * CC;

    for (int t = tid; t < 64 * KK; t += 128)
        selS[t] = g_sel[(size_t)tile * 64 * KK + t];

    const int u  = tid & 15, qr = tid >> 4;   // staging: channel-float4 u, pixel group qr
    const int og = tid >> 4, qs = tid & 15;   // compute: o-group, q residue

    float2 acc[8][4];
#pragma unroll
    for (int j = 0; j < 8; j++)
#pragma unroll
        for (int i = 0; i < 4; i++) acc[j][i] = make_float2(0.f, 0.f);

    float4 pg[8];

    auto cpW = [&](int kc, int bufi) {
        const float* src = g_wP + kc * 4096;
        float* dst = Ws + bufi * WS_CH;
#pragma unroll
        for (int i = 0; i < 8; i++) {
            int g = tid + i * 128;                 // float4 group 0..1023
            int m2 = g >> 5, r = g & 31;
            int og_ = r >> 2, c4 = r & 3;
            cp16(dst + m2 * 160 + og_ * 20 + c4 * 4, src + 4 * g);
        }
        asm volatile("cp.async.commit_group;\n");
    };

    auto ldG = [&](int kc) {
#pragma unroll
        for (int s = 0; s < 8; s++) {
            int q = qr * 8 + s;
            int row = selS[q * KK + kc];
            pg[s] = *(const float4*)(xb + (size_t)row * CC + u * 4);
        }
    };
    auto stG = [&]() {
#pragma unroll
        for (int s = 0; s < 8; s++) {
            int q = qr * 8 + s;
            float4 v = pg[s];
            *(float2*)(Gd + (2 * u    ) * GR + 2 * q) = make_float2(v.x, v.y);
            *(float2*)(Gd + (2 * u + 1) * GR + 2 * q) = make_float2(v.z, v.w);
        }
    };

    // prologue
    cpW(0, 0);
    __syncthreads();            // selS visible
    ldG(0);

    for (int kc = 0; kc < KK; kc++) {
        int buf = kc & 1;
        asm volatile("cp.async.wait_group 0;\n");
        stG();
        __syncthreads();        // Gd + Ws(buf) ready
        if (kc + 1 < KK) {
            ldG(kc + 1);                 // register prefetch overlaps compute
            cpW(kc + 1, buf ^ 1);
        }
        const float* Wsb = Ws + buf * WS_CH;
#pragma unroll 8
        for (int m2 = 0; m2 < 32; m2++) {
            const float* wrow = Wsb + m2 * 160 + og * 20;
            const float* grow = Gd + m2 * GR;
            float4 wq[4];
            float2 gq[4];
#pragma unroll
            for (int jj = 0; jj < 4; jj++)
                wq[jj] = *(const float4*)(wrow + 4 * jj);
#pragma unroll
            for (int ii = 0; ii < 4; ii++)
                gq[ii] = *(const float2*)(grow + 2 * (qs + 16 * ii));
#pragma unroll
            for (int jj = 0; jj < 4; jj++) {
                float2 wA = make_float2(wq[jj].x, wq[jj].y);
                float2 wB = make_float2(wq[jj].z, wq[jj].w);
#pragma unroll
                for (int ii = 0; ii < 4; ii++) {
                    acc[2 * jj][ii]     = ffma2(wA, gq[ii], acc[2 * jj][ii]);
                    acc[2 * jj + 1][ii] = ffma2(wB, gq[ii], acc[2 * jj + 1][ii]);
                }
            }
        }
        __syncthreads();        // compute done before next stG overwrites Gd
    }

    // epilogue: out[b][o][p0 + qs + 16i], fold parity halves
    float* ob = out + (size_t)b * CC * PP + p0;
#pragma unroll
    for (int j = 0; j < 8; j++) {
        int o = og * 8 + j;
#pragma unroll
        for (int i = 0; i < 4; i++)
            ob[(size_t)o * PP + qs + 16 * i] = acc[j][i].x + acc[j][i].y;
    }
}

// ---------------------------------------------------------------------------
extern "C" void kernel_launch(void* const* d_in, const int* in_sizes, int n_in,
                              void* d_out, int out_size) {
    const float* x = (const float*)d_in[0];   // [8,64,56,56]
    const float* w = (const float*)d_in[1];   // [64,64,3,3]
    float* out = (float*)d_out;               // [8,64,56,56]

    cudaFuncSetAttribute(conv4_kernel,
                         cudaFuncAttributeMaxDynamicSharedMemorySize, SMEM4);

    prep_kernel<<<793, 256>>>(x, w);
    simsel2_kernel<<<dim3(7, 56, 8), 256>>>();
    conv4_kernel<<<392, 128, SMEM4>>>(out);
}

// round 11
// speedup vs baseline: 1.3457x; 1.0110x over previous
#include <cuda_runtime.h>

#define HH 56
#define WW 56
#define PP 3136   // HH*WW
#define BB 8
#define CC 64
#define KK 9      // 3x3

// Scratch (device globals: no allocation allowed in kernel_launch)
__device__ float g_xT[BB * PP * CC];    // x transposed: [b][p][c], c contiguous
__device__ float g_invn[BB * PP];       // 1/||x[b,:,p]||
__device__ int   g_sel[BB * PP * KK];   // sorted selected pixel indices
// W reordered: [k][m2][og][j], j 0..15: o = og*8 + (j>>1), c = 2*m2 + (j&1)
__device__ float g_wP[KK * 64 * 64];

// ---------------------------------------------------------------------------
// packed dual-FP32 FMA (Blackwell f32x2 path)
// ---------------------------------------------------------------------------
__device__ __forceinline__ float2 ffma2(float2 a, float2 b, float2 c) {
    unsigned long long A, Bv, Cv;
    A  = *reinterpret_cast<unsigned long long*>(&a);
    Bv = *reinterpret_cast<unsigned long long*>(&b);
    Cv = *reinterpret_cast<unsigned long long*>(&c);
    unsigned long long R;
    asm("fma.rn.f32x2 %0, %1, %2, %3;" : "=l"(R) : "l"(A), "l"(Bv), "l"(Cv));
    return *reinterpret_cast<float2*>(&R);
}

__device__ __forceinline__ void cp16(void* sdst, const void* gsrc) {
    unsigned sa = (unsigned)__cvta_generic_to_shared(sdst);
    asm volatile("cp.async.cg.shared.global [%0], [%1], 16;\n" :: "r"(sa), "l"(gsrc));
}

// ---------------------------------------------------------------------------
// 1) prep2: blocks [0,392) transpose 64px x 64ch with MLP=4 + fused invnorm;
//    blocks [392,401) reorder weights.
// ---------------------------------------------------------------------------
__global__ void __launch_bounds__(256)
prep2_kernel(const float* __restrict__ x, const float* __restrict__ wgt) {
    const int id = blockIdx.x;
    const int t = threadIdx.x;

    if (id >= 392) {            // --- wprep: one block per k ---
        int k = id - 392;
#pragma unroll
        for (int s = 0; s < 16; s++) {
            int r = t * 16 + s;            // 0..4095
            int m2 = r >> 7, og = (r >> 4) & 7, j = r & 15;
            int o = og * 8 + (j >> 1);
            int c = 2 * m2 + (j & 1);
            g_wP[k * 4096 + r] = wgt[o * 576 + c * 9 + k];
        }
        return;
    }

    // --- transpose tile: 64 pixels x 64 channels, 4 LDG.128 in flight ---
    __shared__ float s[64][67];
    int b = id / 49, pt = id - b * 49;
    int p0 = pt * 64;
    const float* xb = x + (size_t)b * CC * PP;
    float* xTb = g_xT + (size_t)b * PP * CC;

    const int v = t & 15, c0 = t >> 4;
    float4 ld[4];
#pragma unroll
    for (int i = 0; i < 4; i++)
        ld[i] = *(const float4*)(xb + (size_t)(c0 + 16 * i) * PP + p0 + 4 * v);
#pragma unroll
    for (int i = 0; i < 4; i++) {
        int c = c0 + 16 * i;
        s[c][4 * v + 0] = ld[i].x; s[c][4 * v + 1] = ld[i].y;
        s[c][4 * v + 2] = ld[i].z; s[c][4 * v + 3] = ld[i].w;
    }
    __syncthreads();

    const int p_l = t >> 4, v2 = t & 15;
#pragma unroll
    for (int i = 0; i < 4; i++) {
        int p = p_l + 16 * i;
        float4 o;
        o.x = s[4 * v2 + 0][p]; o.y = s[4 * v2 + 1][p];
        o.z = s[4 * v2 + 2][p]; o.w = s[4 * v2 + 3][p];
        *(float4*)(xTb + (size_t)(p0 + p) * CC + 4 * v2) = o;

        float sum = o.x * o.x + o.y * o.y + o.z * o.z + o.w * o.w;
        sum += __shfl_xor_sync(0xffffffffu, sum, 1);
        sum += __shfl_xor_sync(0xffffffffu, sum, 2);
        sum += __shfl_xor_sync(0xffffffffu, sum, 4);
        sum += __shfl_xor_sync(0xffffffffu, sum, 8);
        if (v2 == 0) g_invn[b * PP + p0 + p] = 1.0f / sqrtf(sum);
    }
}

// ---------------------------------------------------------------------------
// 3) simsel (unchanged from R7)
// ---------------------------------------------------------------------------
#define SROW 68   // smem row stride (floats)

__global__ void __launch_bounds__(256)
simsel2_kernel() {
    __shared__ __align__(16) float sn[60 * SROW];

    const int t = threadIdx.x;
    const int j0 = blockIdx.x * 8;      // 56/8 = 7 exact
    const int i  = blockIdx.y;
    const int b  = blockIdx.z;
    const float* xb   = g_xT + (size_t)b * PP * CC;
    const float* invb = g_invn + b * PP;

    {
        int slot = t >> 2, q = t & 3;
        if (slot < 60) {
            int ri = slot / 12, rj = slot - ri * 12;
            int gi = i - 2 + ri, gj = j0 - 2 + rj;
            if (gi >= 0 && gi < HH && gj >= 0 && gj < WW) {
                int gp = gi * WW + gj;
                const float* src = xb + (size_t)gp * CC;
                float iv = invb[gp];
                float* dst = sn + slot * SROW;
#pragma unroll
                for (int s = 0; s < 4; s++) {
                    int chunk = q + 4 * s;
                    float4 v = *(const float4*)(src + chunk * 4);
                    v.x *= iv; v.y *= iv; v.z *= iv; v.w *= iv;
                    *(float4*)(dst + 4 * ((chunk + ri) & 15)) = v;
                }
            }
        }
    }
    __syncthreads();

    const int lane = t & 31, w = t >> 5;
    const int j = j0 + w;

    int lo_i = (i - 2 < 0) ? 0 : i - 2;
    int hi_i = (i + 2 > HH - 1) ? HH - 1 : i + 2;
    int lo_j = (j - 2 < 0) ? 0 : j - 2;
    int hi_j = (j + 2 > WW - 1) ? WW - 1 : j + 2;
    int nrow = hi_i - lo_i + 1, ncol = hi_j - lo_j + 1;
    int ncand = nrow * ncol;

    unsigned mult = (65536u + (unsigned)ncol - 1) / (unsigned)ncol;
    int cr = (int)(((unsigned)lane * mult) >> 16);
    int cc = lane - cr * ncol;
    int ri = (lo_i - (i - 2)) + cr;
    int rj = (lo_j - (j0 - 2)) + cc;
    int slot = ri * 12 + rj;
    int rot_c = ri;
    if (lane >= ncand) { slot = 0; rot_c = 0; }
    int cpix = (lo_i + cr) * WW + (lo_j + cc);

    const float* crow = sn + slot * SROW;
    const float* prow = sn + (2 * 12 + (w + 2)) * SROW;   // rot_p = 2

    int idx_c = rot_c & 15;
    int idx_p = 2;

    float2 aA = make_float2(0.f, 0.f), aB = make_float2(0.f, 0.f);
#pragma unroll
    for (int s = 0; s < 16; s++) {
        float4 cv = *(const float4*)(crow + 4 * idx_c);
        float4 pv = *(const float4*)(prow + 4 * idx_p);
        aA = ffma2(make_float2(cv.x, cv.y), make_float2(pv.x, pv.y), aA);
        aB = ffma2(make_float2(cv.z, cv.w), make_float2(pv.z, pv.w), aB);
        idx_c = (idx_c + 1) & 15;
        idx_p = (idx_p + 1) & 15;
    }
    float sim = (aA.x + aB.x) + (aA.y + aB.y);

    unsigned ub = __float_as_uint(sim);
    unsigned key = (ub & 0x80000000u) ? ~ub : (ub | 0x80000000u);
    if (lane >= ncand) key = 0xFFFFFFFFu;

    int mypick = 0;
#pragma unroll
    for (int r = 0; r < KK; r++) {
        unsigned m = __reduce_min_sync(0xffffffffu, key);
        unsigned ball = __ballot_sync(0xffffffffu, key == m);
        int bl = __ffs(ball) - 1;
        int wc = __shfl_sync(0xffffffffu, cpix, bl);
        if (lane == bl) key = 0xFFFFFFFFu;
        if (lane == r) mypick = wc;
    }

    int rank = 0;
#pragma unroll
    for (int r = 0; r < KK; r++) {
        int other = __shfl_sync(0xffffffffu, mypick, r);
        if (lane < KK && r != lane && other < mypick) rank++;
    }
    if (lane < KK)
        g_sel[((size_t)(b * PP + i * WW + j)) * KK + rank] = mypick;
}

// ---------------------------------------------------------------------------
// 4) conv5: tile 64o x 64q, 128 threads, thread tile 8o x 4q, m-paired f32x2.
//    Ws UNPADDED (wq reads are og-broadcast: <=2 distinct addrs/warp, padding
//    was useless) -> freed smem double-buffers Gd -> ONE barrier per k-chunk.
//    smem 68.4KB -> 3 blocks/SM (12 warps).
// ---------------------------------------------------------------------------
#define WS_CH 4096          // floats per Ws chunk (32 m2 x 8 og x 16)
#define GR 130              // Gd floats per m2 row (65 float2: 64 q + pad)
#define GD_CH (32 * GR)     // 4160 floats per Gd buffer
#define SEL5_B 2304
#define SMEM5 (SEL5_B + 2 * WS_CH * 4 + 2 * GD_CH * 4)   // 68352 B

__global__ void __launch_bounds__(128)
conv5_kernel(float* __restrict__ out) {
    extern __shared__ __align__(16) char smem_raw[];
    int*   selS = (int*)smem_raw;
    float* Ws   = (float*)(smem_raw + SEL5_B);
    float* Gd   = (float*)(smem_raw + SEL5_B + 2 * WS_CH * 4);

    const int tid  = threadIdx.x;
    const int tile = blockIdx.x;            // 392 tiles of 64 pixels
    const int b    = tile / 49;
    const int p0   = (tile % 49) * 64;
    const float* xb = g_xT + (size_t)b * PP * CC;

    for (int t = tid; t < 64 * KK; t += 128)
        selS[t] = g_sel[(size_t)tile * 64 * KK + t];

    const int u  = tid & 15, qr = tid >> 4;   // staging roles
    const int og = tid >> 4, qs = tid & 15;   // compute roles

    float2 acc[8][4];
#pragma unroll
    for (int j = 0; j < 8; j++)
#pragma unroll
        for (int i = 0; i < 4; i++) acc[j][i] = make_float2(0.f, 0.f);

    float4 pg[8];

    auto cpW = [&](int kc, int bufi) {
        const float* src = g_wP + kc * 4096;
        float* dst = Ws + bufi * WS_CH;
#pragma unroll
        for (int i = 0; i < 8; i++) {
            int e = (tid + i * 128) * 4;
            cp16(dst + e, src + e);
        }
        asm volatile("cp.async.commit_group;\n");
    };

    auto ldG = [&](int kc) {
#pragma unroll
        for (int s = 0; s < 8; s++) {
            int q = qr * 8 + s;
            int row = selS[q * KK + kc];
            pg[s] = *(const float4*)(xb + (size_t)row * CC + u * 4);
        }
    };
    auto stG = [&](int bufi) {
        float* gd = Gd + bufi * GD_CH;
#pragma unroll
        for (int s = 0; s < 8; s++) {
            int q = qr * 8 + s;
            float4 v = pg[s];
            *(float2*)(gd + (2 * u    ) * GR + 2 * q) = make_float2(v.x, v.y);
            *(float2*)(gd + (2 * u + 1) * GR + 2 * q) = make_float2(v.z, v.w);
        }
    };

    // prologue: W chunk 0 + G chunk 0 into buffer 0
    cpW(0, 0);
    __syncthreads();            // selS visible
    ldG(0);
    stG(0);
    asm volatile("cp.async.wait_group 0;\n");
    __syncthreads();            // buf0 (G+W) ready

    for (int kc = 0; kc < KK; kc++) {
        int buf = kc & 1;
        if (kc + 1 < KK) {
            ldG(kc + 1);                 // register prefetch overlaps compute
            cpW(kc + 1, buf ^ 1);
        }
        const float* Wsb = Ws + buf * WS_CH;
        const float* Gdb = Gd + buf * GD_CH;
#pragma unroll 8
        for (int m2 = 0; m2 < 32; m2++) {
            const float* wrow = Wsb + m2 * 128 + og * 16;
            const float* grow = Gdb + m2 * GR;
            float4 wq[4];
            float2 gq[4];
#pragma unroll
            for (int jj = 0; jj < 4; jj++)
                wq[jj] = *(const float4*)(wrow + 4 * jj);
#pragma unroll
            for (int ii = 0; ii < 4; ii++)
                gq[ii] = *(const float2*)(grow + 2 * (qs + 16 * ii));
#pragma unroll
            for (int jj = 0; jj < 4; jj++) {
                float2 wA = make_float2(wq[jj].x, wq[jj].y);
                float2 wB = make_float2(wq[jj].z, wq[jj].w);
#pragma unroll
                for (int ii = 0; ii < 4; ii++) {
                    acc[2 * jj][ii]     = ffma2(wA, gq[ii], acc[2 * jj][ii]);
                    acc[2 * jj + 1][ii] = ffma2(wB, gq[ii], acc[2 * jj + 1][ii]);
                }
            }
        }
        if (kc + 1 < KK) {
            stG(buf ^ 1);                // write next G while nobody reads it
            asm volatile("cp.async.wait_group 0;\n");
            __syncthreads();             // single barrier per chunk
        }
    }

    // epilogue: out[b][o][p0 + qs + 16i], fold parity halves
    float* ob = out + (size_t)b * CC * PP + p0;
#pragma unroll
    for (int j = 0; j < 8; j++) {
        int o = og * 8 + j;
#pragma unroll
        for (int i = 0; i < 4; i++)
            ob[(size_t)o * PP + qs + 16 * i] = acc[j][i].x + acc[j][i].y;
    }
}

// ---------------------------------------------------------------------------
extern "C" void kernel_launch(void* const* d_in, const int* in_sizes, int n_in,
                              void* d_out, int out_size) {
    const float* x = (const float*)d_in[0];   // [8,64,56,56]
    const float* w = (const float*)d_in[1];   // [64,64,3,3]
    float* out = (float*)d_out;               // [8,64,56,56]

    cudaFuncSetAttribute(conv5_kernel,
                         cudaFuncAttributeMaxDynamicSharedMemorySize, SMEM5);

    prep2_kernel<<<401, 256>>>(x, w);
    simsel2_kernel<<<dim3(7, 56, 8), 256>>>();
    conv5_kernel<<<392, 128, SMEM5>>>(out);
}

// round 14
// speedup vs baseline: 1.5576x; 1.1575x over previous
#include <cuda_runtime.h>
#include <cuda_bf16.h>

#define HH 56
#define WW 56
#define PP 3136   // HH*WW
#define BB 8
#define CC 64
#define KK 9      // 3x3

// Scratch (device globals)
__device__ float g_xT[BB * PP * CC];            // x transposed: [b][p][c]
__device__ float g_invn[BB * PP];               // 1/||x[b,:,p]||
__device__ int   g_sel[BB * PP * KK];           // sorted GLOBAL gather indices
__device__ unsigned short g_wBh[KK * 4096];     // W bf16 hi:  [k][o*64+c]
__device__ unsigned short g_wBl[KK * 4096];     // W bf16 lo residual

// ---------------------------------------------------------------------------
// helpers
// ---------------------------------------------------------------------------
__device__ __forceinline__ float2 ffma2(float2 a, float2 b, float2 c) {
    unsigned long long A, Bv, Cv;
    A  = *reinterpret_cast<unsigned long long*>(&a);
    Bv = *reinterpret_cast<unsigned long long*>(&b);
    Cv = *reinterpret_cast<unsigned long long*>(&c);
    unsigned long long R;
    asm("fma.rn.f32x2 %0, %1, %2, %3;" : "=l"(R) : "l"(A), "l"(Bv), "l"(Cv));
    return *reinterpret_cast<float2*>(&R);
}

__device__ __forceinline__ void cp16(void* sdst, const void* gsrc) {
    unsigned sa = (unsigned)__cvta_generic_to_shared(sdst);
    asm volatile("cp.async.cg.shared.global [%0], [%1], 16;\n" :: "r"(sa), "l"(gsrc));
}

// pack {lo, hi} floats -> bf16x2 (lo in low 16 bits)
__device__ __forceinline__ unsigned bfpack(float lo, float hi) {
    unsigned r;
    asm("cvt.rn.bf16x2.f32 %0, %1, %2;" : "=r"(r) : "f"(hi), "f"(lo));
    return r;
}

__device__ __forceinline__ void ldsm4(unsigned* r, unsigned a) {
    asm volatile("ldmatrix.sync.aligned.m8n8.x4.shared.b16 {%0,%1,%2,%3}, [%4];\n"
        : "=r"(r[0]), "=r"(r[1]), "=r"(r[2]), "=r"(r[3]) : "r"(a));
}

__device__ __forceinline__ void mma_bf16(float* d, const unsigned* a, const unsigned* b) {
    asm volatile(
        "mma.sync.aligned.m16n8k16.row.col.f32.bf16.bf16.f32 "
        "{%0,%1,%2,%3}, {%4,%5,%6,%7}, {%8,%9}, {%0,%1,%2,%3};\n"
        : "+f"(d[0]), "+f"(d[1]), "+f"(d[2]), "+f"(d[3])
        : "r"(a[0]), "r"(a[1]), "r"(a[2]), "r"(a[3]), "r"(b[0]), "r"(b[1]));
}

// ---------------------------------------------------------------------------
// 1) prep: blocks [0,392) transpose 64px x 64ch + invnorm; [392,401) w split
// ---------------------------------------------------------------------------
__global__ void __launch_bounds__(256)
prep2_kernel(const float* __restrict__ x, const float* __restrict__ wgt) {
    const int id = blockIdx.x;
    const int t = threadIdx.x;

    if (id >= 392) {            // --- weight bf16 hi/lo split, [k][o*64+c] ---
        int k = id - 392;
#pragma unroll
        for (int s = 0; s < 16; s++) {
            int r = t * 16 + s;            // 0..4095
            int o = r >> 6, c = r & 63;
            float w = wgt[o * 576 + c * 9 + k];
            unsigned hp = bfpack(w, 0.0f);
            float res = w - __uint_as_float(hp << 16);
            unsigned lp = bfpack(res, 0.0f);
            g_wBh[k * 4096 + r] = (unsigned short)(hp & 0xFFFFu);
            g_wBl[k * 4096 + r] = (unsigned short)(lp & 0xFFFFu);
        }
        return;
    }

    __shared__ float s[64][67];
    int b = id / 49, pt = id - b * 49;
    int p0 = pt * 64;
    const float* xb = x + (size_t)b * CC * PP;
    float* xTb = g_xT + (size_t)b * PP * CC;

    const int v = t & 15, c0 = t >> 4;
    float4 ld[4];
#pragma unroll
    for (int i = 0; i < 4; i++)
        ld[i] = *(const float4*)(xb + (size_t)(c0 + 16 * i) * PP + p0 + 4 * v);
#pragma unroll
    for (int i = 0; i < 4; i++) {
        int c = c0 + 16 * i;
        s[c][4 * v + 0] = ld[i].x; s[c][4 * v + 1] = ld[i].y;
        s[c][4 * v + 2] = ld[i].z; s[c][4 * v + 3] = ld[i].w;
    }
    __syncthreads();

    const int p_l = t >> 4, v2 = t & 15;
#pragma unroll
    for (int i = 0; i < 4; i++) {
        int p = p_l + 16 * i;
        float4 o;
        o.x = s[4 * v2 + 0][p]; o.y = s[4 * v2 + 1][p];
        o.z = s[4 * v2 + 2][p]; o.w = s[4 * v2 + 3][p];
        *(float4*)(xTb + (size_t)(p0 + p) * CC + 4 * v2) = o;

        float sum = o.x * o.x + o.y * o.y + o.z * o.z + o.w * o.w;
        sum += __shfl_xor_sync(0xffffffffu, sum, 1);
        sum += __shfl_xor_sync(0xffffffffu, sum, 2);
        sum += __shfl_xor_sync(0xffffffffu, sum, 4);
        sum += __shfl_xor_sync(0xffffffffu, sum, 8);
        if (v2 == 0) g_invn[b * PP + p0 + p] = 1.0f / sqrtf(sum);
    }
}

// ---------------------------------------------------------------------------
// 3) simsel (R7 structure; stores GLOBAL pixel indices b*PP + pick)
// ---------------------------------------------------------------------------
#define SROW 68

__global__ void __launch_bounds__(256)
simsel2_kernel() {
    __shared__ __align__(16) float sn[60 * SROW];

    const int t = threadIdx.x;
    const int j0 = blockIdx.x * 8;
    const int i  = blockIdx.y;
    const int b  = blockIdx.z;
    const float* xb   = g_xT + (size_t)b * PP * CC;
    const float* invb = g_invn + b * PP;

    {
        int slot = t >> 2, q = t & 3;
        if (slot < 60) {
            int ri = slot / 12, rj = slot - ri * 12;
            int gi = i - 2 + ri, gj = j0 - 2 + rj;
            if (gi >= 0 && gi < HH && gj >= 0 && gj < WW) {
                int gp = gi * WW + gj;
                const float* src = xb + (size_t)gp * CC;
                float iv = invb[gp];
                float* dst = sn + slot * SROW;
#pragma unroll
                for (int s = 0; s < 4; s++) {
                    int chunk = q + 4 * s;
                    float4 v = *(const float4*)(src + chunk * 4);
                    v.x *= iv; v.y *= iv; v.z *= iv; v.w *= iv;
                    *(float4*)(dst + 4 * ((chunk + ri) & 15)) = v;
                }
            }
        }
    }
    __syncthreads();

    const int lane = t & 31, w = t >> 5;
    const int j = j0 + w;

    int lo_i = (i - 2 < 0) ? 0 : i - 2;
    int hi_i = (i + 2 > HH - 1) ? HH - 1 : i + 2;
    int lo_j = (j - 2 < 0) ? 0 : j - 2;
    int hi_j = (j + 2 > WW - 1) ? WW - 1 : j + 2;
    int nrow = hi_i - lo_i + 1, ncol = hi_j - lo_j + 1;
    int ncand = nrow * ncol;

    unsigned mult = (65536u + (unsigned)ncol - 1) / (unsigned)ncol;
    int cr = (int)(((unsigned)lane * mult) >> 16);
    int cc = lane - cr * ncol;
    int ri = (lo_i - (i - 2)) + cr;
    int rj = (lo_j - (j0 - 2)) + cc;
    int slot = ri * 12 + rj;
    int rot_c = ri;
    if (lane >= ncand) { slot = 0; rot_c = 0; }
    int cpix = b * PP + (lo_i + cr) * WW + (lo_j + cc);   // GLOBAL index

    const float* crow = sn + slot * SROW;
    const float* prow = sn + (2 * 12 + (w + 2)) * SROW;

    int idx_c = rot_c & 15;
    int idx_p = 2;

    float2 aA = make_float2(0.f, 0.f), aB = make_float2(0.f, 0.f);
#pragma unroll
    for (int s = 0; s < 16; s++) {
        float4 cv = *(const float4*)(crow + 4 * idx_c);
        float4 pv = *(const float4*)(prow + 4 * idx_p);
        aA = ffma2(make_float2(cv.x, cv.y), make_float2(pv.x, pv.y), aA);
        aB = ffma2(make_float2(cv.z, cv.w), make_float2(pv.z, pv.w), aB);
        idx_c = (idx_c + 1) & 15;
        idx_p = (idx_p + 1) & 15;
    }
    float sim = (aA.x + aB.x) + (aA.y + aB.y);

    unsigned ub = __float_as_uint(sim);
    unsigned key = (ub & 0x80000000u) ? ~ub : (ub | 0x80000000u);
    if (lane >= ncand) key = 0xFFFFFFFFu;

    int mypick = 0;
#pragma unroll
    for (int r = 0; r < KK; r++) {
        unsigned m = __reduce_min_sync(0xffffffffu, key);
        unsigned ball = __ballot_sync(0xffffffffu, key == m);
        int bl = __ffs(ball) - 1;
        int wc = __shfl_sync(0xffffffffu, cpix, bl);
        if (lane == bl) key = 0xFFFFFFFFu;
        if (lane == r) mypick = wc;
    }

    int rank = 0;
#pragma unroll
    for (int r = 0; r < KK; r++) {
        int other = __shfl_sync(0xffffffffu, mypick, r);
        if (lane < KK && r != lane && other < mypick) rank++;
    }
    if (lane < KK)
        g_sel[((size_t)(b * PP + i * WW + j)) * KK + rank] = mypick;
}

// ---------------------------------------------------------------------------
// 4) conv_mma: HMMA (mma.sync m16n8k16 bf16) split-product GEMM.
//    Tile 128px x 64o, 8 warps (warp tile 32x32). A/B staged in smem with
//    144B rows (9x16B, odd granules -> ldmatrix conflict-free).
//    D = Ah*Bh + Al*Bh + Ah*Bl in fp32 accumulators.
// ---------------------------------------------------------------------------
#define CM_SEL  0
#define CM_GH   4608                  // 128 rows * 144B
#define CM_GL   (CM_GH + 18432)
#define CM_WH   (CM_GL + 18432)       // 64 rows * 144B
#define CM_WL   (CM_WH + 9216)
#define CM_SMEM (CM_WL + 9216)        // 59904 B

__global__ void __launch_bounds__(256)
conv_mma_kernel(float* __restrict__ out) {
    extern __shared__ __align__(128) char sm[];
    unsigned sbase = (unsigned)__cvta_generic_to_shared(sm);
    int* selS = (int*)(sm + CM_SEL);

    const int tid = threadIdx.x;
    const int wid = tid >> 5, lane = tid & 31;
    const int tile = blockIdx.x;           // 196 tiles of 128 pixels

    for (int t2 = tid; t2 < 128 * KK; t2 += 256)
        selS[t2] = g_sel[(size_t)tile * 128 * KK + t2];

    const int qrow = tid >> 1;             // 0..127 pixel row (staging)
    const int ch0 = (tid & 1) * 32;        // channel half (staging)

    const int m0 = (wid & 3) * 32;         // warp pixel offset
    const int n0 = (wid >> 2) * 32;        // warp o offset

    // ldmatrix per-lane addresses
    const int arow = (lane & 7) + 8 * ((lane >> 3) & 1);
    const unsigned acol = (unsigned)(lane >> 4) * 16;
    const int brow = (lane & 7) + 8 * (lane >> 4);
    const unsigned bcol = (unsigned)((lane >> 3) & 1) * 16;

    const unsigned aAH0 = sbase + CM_GH + (unsigned)(m0 + arow) * 144 + acol;
    const unsigned aAH1 = aAH0 + 16 * 144;
    const unsigned aAL0 = aAH0 + (CM_GL - CM_GH);
    const unsigned aAL1 = aAH1 + (CM_GL - CM_GH);
    const unsigned aBH0 = sbase + CM_WH + (unsigned)(n0 + brow) * 144 + bcol;
    const unsigned aBH1 = aBH0 + 16 * 144;
    const unsigned aBL0 = aBH0 + (CM_WL - CM_WH);
    const unsigned aBL1 = aBH1 + (CM_WL - CM_WH);

    float acc[2][4][4];
#pragma unroll
    for (int mf = 0; mf < 2; mf++)
#pragma unroll
        for (int nf = 0; nf < 4; nf++)
#pragma unroll
            for (int r = 0; r < 4; r++) acc[mf][nf][r] = 0.0f;

    __syncthreads();   // selS visible

    for (int kc = 0; kc < KK; kc++) {
        // --- stage W hi/lo via cp.async (pre-split; 512 16B chunks each) ---
#pragma unroll
        for (int i = 0; i < 2; i++) {
            int e = tid + i * 256;             // 0..511
            int row = e >> 3, c16 = e & 7;
            unsigned doff = (unsigned)row * 144 + (unsigned)c16 * 16;
            cp16(sm + CM_WH + doff, (const char*)g_wBh + (size_t)kc * 8192 + (size_t)e * 16);
            cp16(sm + CM_WL + doff, (const char*)g_wBl + (size_t)kc * 8192 + (size_t)e * 16);
        }
        asm volatile("cp.async.commit_group;\n");

        // --- stage A: gather row, split to bf16 hi/lo ---
        {
            int rowg = selS[qrow * KK + kc];
            const float4* src = (const float4*)(g_xT + (size_t)rowg * CC + ch0);
#pragma unroll
            for (int g = 0; g < 8; g++) {
                float4 v = src[g];
                unsigned h01 = bfpack(v.x, v.y);
                unsigned h23 = bfpack(v.z, v.w);
                float r0 = v.x - __uint_as_float(h01 << 16);
                float r1 = v.y - __uint_as_float(h01 & 0xFFFF0000u);
                float r2 = v.z - __uint_as_float(h23 << 16);
                float r3 = v.w - __uint_as_float(h23 & 0xFFFF0000u);
                unsigned l01 = bfpack(r0, r1);
                unsigned l23 = bfpack(r2, r3);
                unsigned off = (unsigned)qrow * 144 + (unsigned)(ch0 + 4 * g) * 2;
                *(uint2*)(sm + CM_GH + off) = make_uint2(h01, h23);
                *(uint2*)(sm + CM_GL + off) = make_uint2(l01, l23);
            }
        }
        asm volatile("cp.async.wait_group 0;\n");
        __syncthreads();

        // --- compute: 4 k-steps of 16 ---
#pragma unroll
        for (int s = 0; s < 4; s++) {
            unsigned ks = (unsigned)s * 32;
            unsigned ah0[4], ah1[4], b0[4], b1[4], t0[4], t1[4];
            ldsm4(ah0, aAH0 + ks);
            ldsm4(ah1, aAH1 + ks);
            ldsm4(b0, aBH0 + ks);          // {nf0.b0, nf0.b1, nf1.b0, nf1.b1}
            ldsm4(b1, aBH1 + ks);          // nf2, nf3
            // Ah * Bh
            mma_bf16(acc[0][0], ah0, b0);     mma_bf16(acc[0][1], ah0, b0 + 2);
            mma_bf16(acc[0][2], ah0, b1);     mma_bf16(acc[0][3], ah0, b1 + 2);
            mma_bf16(acc[1][0], ah1, b0);     mma_bf16(acc[1][1], ah1, b0 + 2);
            mma_bf16(acc[1][2], ah1, b1);     mma_bf16(acc[1][3], ah1, b1 + 2);
            // Al * Bh
            ldsm4(t0, aAL0 + ks);
            ldsm4(t1, aAL1 + ks);
            mma_bf16(acc[0][0], t0, b0);      mma_bf16(acc[0][1], t0, b0 + 2);
            mma_bf16(acc[0][2], t0, b1);      mma_bf16(acc[0][3], t0, b1 + 2);
            mma_bf16(acc[1][0], t1, b0);      mma_bf16(acc[1][1], t1, b0 + 2);
            mma_bf16(acc[1][2], t1, b1);      mma_bf16(acc[1][3], t1, b1 + 2);
            // Ah * Bl
            ldsm4(b0, aBL0 + ks);
            ldsm4(b1, aBL1 + ks);
            mma_bf16(acc[0][0], ah0, b0);     mma_bf16(acc[0][1], ah0, b0 + 2);
            mma_bf16(acc[0][2], ah0, b1);     mma_bf16(acc[0][3], ah0, b1 + 2);
            mma_bf16(acc[1][0], ah1, b0);     mma_bf16(acc[1][1], ah1, b0 + 2);
            mma_bf16(acc[1][2], ah1, b1);     mma_bf16(acc[1][3], ah1, b1 + 2);
        }
        __syncthreads();    // all reads done before next chunk overwrites
    }

    // --- epilogue: C[px][o] -> out[b][o][p] ---
#pragma unroll
    for (int mf = 0; mf < 2; mf++) {
        int q0p = tile * 128 + m0 + 16 * mf + (lane >> 2);
        int q1p = q0p + 8;
        int b0i = q0p / PP, b1i = q1p / PP;
        float* ptr0 = out + (size_t)b0i * CC * PP + (q0p - b0i * PP);
        float* ptr1 = out + (size_t)b1i * CC * PP + (q1p - b1i * PP);
#pragma unroll
        for (int nf = 0; nf < 4; nf++) {
            int o = n0 + 8 * nf + (lane & 3) * 2;
            ptr0[(size_t)o * PP]       = acc[mf][nf][0];
            ptr0[(size_t)(o + 1) * PP] = acc[mf][nf][1];
            ptr1[(size_t)o * PP]       = acc[mf][nf][2];
            ptr1[(size_t)(o + 1) * PP] = acc[mf][nf][3];
        }
    }
}

// ---------------------------------------------------------------------------
extern "C" void kernel_launch(void* const* d_in, const int* in_sizes, int n_in,
                              void* d_out, int out_size) {
    const float* x = (const float*)d_in[0];   // [8,64,56,56]
    const float* w = (const float*)d_in[1];   // [64,64,3,3]
    float* out = (float*)d_out;               // [8,64,56,56]

    cudaFuncSetAttribute(conv_mma_kernel,
                         cudaFuncAttributeMaxDynamicSharedMemorySize, CM_SMEM);

    prep2_kernel<<<401, 256>>>(x, w);
    simsel2_kernel<<<dim3(7, 56, 8), 256>>>();
    conv_mma_kernel<<<196, 256, CM_SMEM>>>(out);
}